// round 1
// baseline (speedup 1.0000x reference)
#include <cuda_runtime.h>
#include <cstdint>

// Problem constants (match reference)
#define NUM_USERS 150000
#define NUM_ITEMS 80000
#define N_NODES   230000
#define NNZ       5000000
#define DIM       64
#define NFLOATS   (N_NODES * DIM)        // 14,720,000 floats
#define NVEC4     (NFLOATS / 4)          // 3,680,000 float4

// Scratch ping-pong buffers (allocation-free: __device__ globals)
__device__ float g_bufA[NFLOATS];
__device__ float g_bufB[NFLOATS];

// ---------------------------------------------------------------------------
// init: out = x0 = concat(user, item); bufA = x0; bufB = 0
// ---------------------------------------------------------------------------
__global__ void init_kernel(const float4* __restrict__ user,
                            const float4* __restrict__ item,
                            float4* __restrict__ out) {
    int i = blockIdx.x * blockDim.x + threadIdx.x;
    if (i >= NVEC4) return;
    const int usz = NUM_USERS * DIM / 4;
    float4 v = (i < usz) ? user[i] : item[i - usz];
    out[i] = v;
    reinterpret_cast<float4*>(g_bufA)[i] = v;
    reinterpret_cast<float4*>(g_bufB)[i] = make_float4(0.f, 0.f, 0.f, 0.f);
}

// ---------------------------------------------------------------------------
// SpMM: dst[rows[e], :] += vals[e] * src[cols[e], :]
// 16 threads per edge, float4 lanes, vector REDG (fire-and-forget atomic).
// DIR=0: A -> B ; DIR=1: B -> A
// ---------------------------------------------------------------------------
template <int DIR>
__global__ void spmm_kernel(const int*   __restrict__ rows,
                            const int*   __restrict__ cols,
                            const float* __restrict__ vals) {
    const float* __restrict__ src = DIR ? g_bufB : g_bufA;
    float*       __restrict__ dst = DIR ? g_bufA : g_bufB;

    long long gid = (long long)blockIdx.x * blockDim.x + threadIdx.x;
    int e = (int)(gid >> 4);
    if (e >= NNZ) return;
    int sub = ((int)gid) & 15;          // 0..15 -> float4 slot

    int   r = __ldg(rows + e);
    int   c = __ldg(cols + e);
    float v = __ldg(vals + e);

    float4 x = *reinterpret_cast<const float4*>(src + (size_t)c * DIM + sub * 4);
    float a0 = x.x * v, a1 = x.y * v, a2 = x.z * v, a3 = x.w * v;

    float* dp = dst + (size_t)r * DIM + sub * 4;
    asm volatile("red.global.add.v4.f32 [%0], {%1, %2, %3, %4};"
                 :: "l"(dp), "f"(a0), "f"(a1), "f"(a2), "f"(a3)
                 : "memory");
}

// ---------------------------------------------------------------------------
// accumulate freshly computed layer into out, and zero the OTHER buffer
// (which becomes the next layer's destination). One pass instead of two.
// SRC=0: read B, zero A ; SRC=1: read A, zero B
// ---------------------------------------------------------------------------
template <int SRC>
__global__ void accum_zero_kernel(float4* __restrict__ out) {
    int i = blockIdx.x * blockDim.x + threadIdx.x;
    if (i >= NVEC4) return;
    const float4* __restrict__ fresh =
        reinterpret_cast<const float4*>(SRC ? g_bufA : g_bufB);
    float4* __restrict__ tozero =
        reinterpret_cast<float4*>(SRC ? g_bufB : g_bufA);
    float4 o = out[i];
    float4 f = fresh[i];
    o.x += f.x; o.y += f.y; o.z += f.z; o.w += f.w;
    out[i] = o;
    tozero[i] = make_float4(0.f, 0.f, 0.f, 0.f);
}

// final: out = (out + fresh(B)) * 0.25
__global__ void accum_scale_kernel(float4* __restrict__ out) {
    int i = blockIdx.x * blockDim.x + threadIdx.x;
    if (i >= NVEC4) return;
    const float4* __restrict__ fresh = reinterpret_cast<const float4*>(g_bufB);
    float4 o = out[i];
    float4 f = fresh[i];
    o.x = (o.x + f.x) * 0.25f;
    o.y = (o.y + f.y) * 0.25f;
    o.z = (o.z + f.z) * 0.25f;
    o.w = (o.w + f.w) * 0.25f;
    out[i] = o;
}

// ---------------------------------------------------------------------------
extern "C" void kernel_launch(void* const* d_in, const int* in_sizes, int n_in,
                              void* d_out, int out_size) {
    const float* user = (const float*)d_in[0];
    const float* item = (const float*)d_in[1];
    const int*   rows = (const int*)d_in[2];
    const int*   cols = (const int*)d_in[3];
    const float* vals = (const float*)d_in[4];
    float* out = (float*)d_out;

    const int TB = 256;
    const int elemGrid = (NVEC4 + TB - 1) / TB;                    // 14375
    const long long spmmThreads = (long long)NNZ * 16;             // 80M
    const int spmmGrid = (int)((spmmThreads + TB - 1) / TB);       // 312500

    // out = x0; A = x0; B = 0
    init_kernel<<<elemGrid, TB>>>((const float4*)user, (const float4*)item,
                                  (float4*)out);

    // layer 1: x1 = A*x0  (A -> B)
    spmm_kernel<0><<<spmmGrid, TB>>>(rows, cols, vals);
    accum_zero_kernel<0><<<elemGrid, TB>>>((float4*)out);  // out += B, zero A

    // layer 2: x2 (B -> A)
    spmm_kernel<1><<<spmmGrid, TB>>>(rows, cols, vals);
    accum_zero_kernel<1><<<elemGrid, TB>>>((float4*)out);  // out += A, zero B

    // layer 3: x3 (A -> B)
    spmm_kernel<0><<<spmmGrid, TB>>>(rows, cols, vals);
    accum_scale_kernel<<<elemGrid, TB>>>((float4*)out);    // out=(out+B)/4
}